// round 6
// baseline (speedup 1.0000x reference)
#include <cuda_runtime.h>

// Cosine-similarity discriminator:
//   out[b, n]     = cos(s_row, h_rl_row)   (torch F.normalize, eps=1e-12)
//   out[b, N + n] = cos(s_row, h_fk_row)
// Shapes: s, h_rl, h_fk : [B=8, N=8192, D=512] fp32 ; out : [B, 2N] fp32.
//
// One warp per row, oversubscribed launch. launch_bounds(128,16) pins regs to
// 32 -> 64 warps/SM; 128-thread CTAs give the work distributor finer refill
// granularity than 256-thread CTAs. Streaming .cs loads (single-use data),
// 5-accumulator dot products, butterfly shuffle reduce.
// (redux.sync.add.f32 is NOT available on sm_103 — shuffle is the fallback.)

#define D 512
#define NROW_N 8192
#define WARPS_PER_BLOCK 4
#define THREADS (WARPS_PER_BLOCK * 32)

__device__ __forceinline__ float4 ldcs4(const float4* p) {
    return __ldcs(p);   // LDG.E.128.CS
}

__global__ __launch_bounds__(THREADS, 16)
void cosine_pair_kernel(const float* __restrict__ s,
                        const float* __restrict__ h_rl,
                        const float* __restrict__ h_fk,
                        float* __restrict__ out,
                        int total_rows)
{
    const int warp_id = blockIdx.x * WARPS_PER_BLOCK + (threadIdx.x >> 5);
    const int lane    = threadIdx.x & 31;
    if (warp_id >= total_rows) return;

    const size_t base = (size_t)warp_id * D;
    const float4* __restrict__ s4 = reinterpret_cast<const float4*>(s    + base);
    const float4* __restrict__ a4 = reinterpret_cast<const float4*>(h_rl + base);
    const float4* __restrict__ b4 = reinterpret_cast<const float4*>(h_fk + base);

    float ss = 0.f, aa = 0.f, bb = 0.f, sa = 0.f, sb = 0.f;

    // 128 float4 per row / 32 lanes = 4 logical iterations; 2 half-batches of
    // 6 prefetched loads each (24 live regs) to stay within 32 regs total.
#pragma unroll
    for (int h = 0; h < 2; ++h) {
        float4 vs0 = ldcs4(&s4[(2 * h + 0) * 32 + lane]);
        float4 va0 = ldcs4(&a4[(2 * h + 0) * 32 + lane]);
        float4 vb0 = ldcs4(&b4[(2 * h + 0) * 32 + lane]);
        float4 vs1 = ldcs4(&s4[(2 * h + 1) * 32 + lane]);
        float4 va1 = ldcs4(&a4[(2 * h + 1) * 32 + lane]);
        float4 vb1 = ldcs4(&b4[(2 * h + 1) * 32 + lane]);

        ss += vs0.x * vs0.x + vs0.y * vs0.y + vs0.z * vs0.z + vs0.w * vs0.w;
        aa += va0.x * va0.x + va0.y * va0.y + va0.z * va0.z + va0.w * va0.w;
        bb += vb0.x * vb0.x + vb0.y * vb0.y + vb0.z * vb0.z + vb0.w * vb0.w;
        sa += vs0.x * va0.x + vs0.y * va0.y + vs0.z * va0.z + vs0.w * va0.w;
        sb += vs0.x * vb0.x + vs0.y * vb0.y + vs0.z * vb0.z + vs0.w * vb0.w;

        ss += vs1.x * vs1.x + vs1.y * vs1.y + vs1.z * vs1.z + vs1.w * vs1.w;
        aa += va1.x * va1.x + va1.y * va1.y + va1.z * va1.z + va1.w * va1.w;
        bb += vb1.x * vb1.x + vb1.y * vb1.y + vb1.z * vb1.z + vb1.w * vb1.w;
        sa += vs1.x * va1.x + vs1.y * va1.y + vs1.z * va1.z + vs1.w * va1.w;
        sb += vs1.x * vb1.x + vs1.y * vb1.y + vs1.z * vb1.z + vs1.w * vb1.w;
    }

    // Butterfly reduction over the 5 partial sums (5 independent chains
    // pipeline; serial depth = 5 SHFL stages).
#pragma unroll
    for (int off = 16; off > 0; off >>= 1) {
        ss += __shfl_xor_sync(0xffffffffu, ss, off);
        aa += __shfl_xor_sync(0xffffffffu, aa, off);
        bb += __shfl_xor_sync(0xffffffffu, bb, off);
        sa += __shfl_xor_sync(0xffffffffu, sa, off);
        sb += __shfl_xor_sync(0xffffffffu, sb, off);
    }

    if (lane == 0) {
        const float eps = 1e-12f;
        const float ns = fmaxf(sqrtf(ss), eps);
        const float na = fmaxf(sqrtf(aa), eps);
        const float nb = fmaxf(sqrtf(bb), eps);

        const int b = warp_id >> 13;             // / 8192
        const int n = warp_id & (NROW_N - 1);    // % 8192
        float* obase = out + (size_t)b * (2 * NROW_N);
        __stcs(&obase[n],          sa / (ns * na));
        __stcs(&obase[NROW_N + n], sb / (ns * nb));
    }
}

extern "C" void kernel_launch(void* const* d_in, const int* in_sizes, int n_in,
                              void* d_out, int out_size)
{
    const float* s    = (const float*)d_in[0];
    const float* h_rl = (const float*)d_in[1];
    const float* h_fk = (const float*)d_in[2];
    float* out = (float*)d_out;

    const int total_rows = in_sizes[0] / D;   // B*N = 65536
    const int blocks = (total_rows + WARPS_PER_BLOCK - 1) / WARPS_PER_BLOCK;

    cosine_pair_kernel<<<blocks, THREADS>>>(s, h_rl, h_fk, out, total_rows);
}

// round 7
// speedup vs baseline: 1.0425x; 1.0425x over previous
#include <cuda_runtime.h>

// Cosine-similarity discriminator — FINAL (HBM-bound at ~6.7/8 TB/s):
//   out[b, n]     = cos(s_row, h_rl_row)   (torch F.normalize, eps=1e-12)
//   out[b, N + n] = cos(s_row, h_fk_row)
// Shapes: s, h_rl, h_fk : [B=8, N=8192, D=512] fp32 ; out : [B, 2N] fp32.
//
// Design (validated over R1-R6):
//  - one warp per row, oversubscribed launch (8192 CTAs); the HW scheduler
//    overlaps retiring warps' reduction tails with fresh warps' loads
//    (explicit persistence regressed: it serializes tails, R2).
//  - __launch_bounds__(256, 8) pins regs to 32 -> 64 warps/SM (R3 win).
//  - .cs evict-first loads/stores: data is single-use (R4, small win).
//  - 2 half-batches of 6 float4 loads (24 live regs) fit the 32-reg budget
//    without spills; full 12-load batch costs occupancy and loses (R1).
//  - butterfly shuffle reduce (redux.sync.add.f32 does not exist on sm_103).

#define D 512
#define NROW_N 8192
#define WARPS_PER_BLOCK 8
#define THREADS (WARPS_PER_BLOCK * 32)

__device__ __forceinline__ float4 ldcs4(const float4* p) {
    return __ldcs(p);   // LDG.E.128.CS
}

__global__ __launch_bounds__(THREADS, 8)
void cosine_pair_kernel(const float* __restrict__ s,
                        const float* __restrict__ h_rl,
                        const float* __restrict__ h_fk,
                        float* __restrict__ out,
                        int total_rows)
{
    const int warp_id = blockIdx.x * WARPS_PER_BLOCK + (threadIdx.x >> 5);
    const int lane    = threadIdx.x & 31;
    if (warp_id >= total_rows) return;

    const size_t base = (size_t)warp_id * D;
    const float4* __restrict__ s4 = reinterpret_cast<const float4*>(s    + base);
    const float4* __restrict__ a4 = reinterpret_cast<const float4*>(h_rl + base);
    const float4* __restrict__ b4 = reinterpret_cast<const float4*>(h_fk + base);

    float ss = 0.f, aa = 0.f, bb = 0.f, sa = 0.f, sb = 0.f;

    // 128 float4 per row / 32 lanes = 4 logical iterations; 2 half-batches of
    // 6 prefetched loads each.
#pragma unroll
    for (int h = 0; h < 2; ++h) {
        float4 vs0 = ldcs4(&s4[(2 * h + 0) * 32 + lane]);
        float4 va0 = ldcs4(&a4[(2 * h + 0) * 32 + lane]);
        float4 vb0 = ldcs4(&b4[(2 * h + 0) * 32 + lane]);
        float4 vs1 = ldcs4(&s4[(2 * h + 1) * 32 + lane]);
        float4 va1 = ldcs4(&a4[(2 * h + 1) * 32 + lane]);
        float4 vb1 = ldcs4(&b4[(2 * h + 1) * 32 + lane]);

        ss += vs0.x * vs0.x + vs0.y * vs0.y + vs0.z * vs0.z + vs0.w * vs0.w;
        aa += va0.x * va0.x + va0.y * va0.y + va0.z * va0.z + va0.w * va0.w;
        bb += vb0.x * vb0.x + vb0.y * vb0.y + vb0.z * vb0.z + vb0.w * vb0.w;
        sa += vs0.x * va0.x + vs0.y * va0.y + vs0.z * va0.z + vs0.w * va0.w;
        sb += vs0.x * vb0.x + vs0.y * vb0.y + vs0.z * vb0.z + vs0.w * vb0.w;

        ss += vs1.x * vs1.x + vs1.y * vs1.y + vs1.z * vs1.z + vs1.w * vs1.w;
        aa += va1.x * va1.x + va1.y * va1.y + va1.z * va1.z + va1.w * va1.w;
        bb += vb1.x * vb1.x + vb1.y * vb1.y + vb1.z * vb1.z + vb1.w * vb1.w;
        sa += vs1.x * va1.x + vs1.y * va1.y + vs1.z * va1.z + vs1.w * va1.w;
        sb += vs1.x * vb1.x + vs1.y * vb1.y + vs1.z * vb1.z + vs1.w * vb1.w;
    }

    // Butterfly reduction over the 5 partial sums (5 independent chains
    // pipeline across the 5 SHFL stages).
#pragma unroll
    for (int off = 16; off > 0; off >>= 1) {
        ss += __shfl_xor_sync(0xffffffffu, ss, off);
        aa += __shfl_xor_sync(0xffffffffu, aa, off);
        bb += __shfl_xor_sync(0xffffffffu, bb, off);
        sa += __shfl_xor_sync(0xffffffffu, sa, off);
        sb += __shfl_xor_sync(0xffffffffu, sb, off);
    }

    if (lane == 0) {
        const float eps = 1e-12f;
        const float ns = fmaxf(sqrtf(ss), eps);
        const float na = fmaxf(sqrtf(aa), eps);
        const float nb = fmaxf(sqrtf(bb), eps);

        const int b = warp_id >> 13;             // / 8192
        const int n = warp_id & (NROW_N - 1);    // % 8192
        float* obase = out + (size_t)b * (2 * NROW_N);
        __stcs(&obase[n],          sa / (ns * na));
        __stcs(&obase[NROW_N + n], sb / (ns * nb));
    }
}

extern "C" void kernel_launch(void* const* d_in, const int* in_sizes, int n_in,
                              void* d_out, int out_size)
{
    const float* s    = (const float*)d_in[0];
    const float* h_rl = (const float*)d_in[1];
    const float* h_fk = (const float*)d_in[2];
    float* out = (float*)d_out;

    const int total_rows = in_sizes[0] / D;   // B*N = 65536
    const int blocks = (total_rows + WARPS_PER_BLOCK - 1) / WARPS_PER_BLOCK;

    cosine_pair_kernel<<<blocks, THREADS>>>(s, h_rl, h_fk, out, total_rows);
}